// round 6
// baseline (speedup 1.0000x reference)
#include <cuda_runtime.h>

// MaxLocaldist: per output pixel, max pairwise L2 distance among the 9 RGB
// pixels of the 3x3 neighborhood. Input (32,3,224,224) f32 NCHW.
// Output (32,1,224,224) f32, 1-pixel zero border.
//
// Row decomposition, thread-per-output-column, ZERO shfls:
//   W(r)      = max d2 among the 3 points of input row r      (3 pairs)
//   X(ra,rb)  = max d2 between rows ra and rb                 (9 pairs)
//   out(h)    = max(W(h-1),W(h),W(h+1), X(h-1,h), X(h-1,h+1), X(h,h+1))
// Sliding h->h+1 carries W(h), W(h+1), X(h,h+1) in 3 registers; only the 12
// pairs involving the new row h+1 are evaluated, packed into fma.rn.f32x2
// (bcast new-row point vs pack2(top-row point, mid-row point)).

#define HD 224
#define WD 224
#define HWD (HD * WD)
#define R_ROWS 8
#define NTILES (HD / R_ROWS)

typedef unsigned long long u64;

__device__ __forceinline__ u64 bcast2(float v) {
    u64 r; asm("mov.b64 %0, {%1, %1};" : "=l"(r) : "f"(v)); return r;
}
__device__ __forceinline__ u64 pack2(float lo, float hi) {
    u64 r; asm("mov.b64 %0, {%1, %2};" : "=l"(r) : "f"(lo), "f"(hi)); return r;
}
__device__ __forceinline__ void unpack2(float& lo, float& hi, u64 v) {
    asm("mov.b64 {%0, %1}, %2;" : "=f"(lo), "=f"(hi) : "l"(v));
}
__device__ __forceinline__ u64 fma2(u64 a, u64 b, u64 c) {
    u64 r; asm("fma.rn.f32x2 %0, %1, %2, %3;" : "=l"(r) : "l"(a), "l"(b), "l"(c));
    return r;
}
__device__ __forceinline__ u64 mul2(u64 a, u64 b) {
    u64 r; asm("mul.rn.f32x2 %0, %1, %2;" : "=l"(r) : "l"(a), "l"(b));
    return r;
}
// packed d2 between broadcast point a and packed point-pair b (exact sub via fma)
__device__ __forceinline__ u64 d2p(const u64 a[3], const u64 b[3], u64 neg1) {
    const u64 d0 = fma2(b[0], neg1, a[0]);
    const u64 d1 = fma2(b[1], neg1, a[1]);
    const u64 d2 = fma2(b[2], neg1, a[2]);
    u64 s = mul2(d2, d2);
    s = fma2(d1, d1, s);
    s = fma2(d0, d0, s);
    return s;
}
__device__ __forceinline__ float d2s(const float a[3], const float b[3]) {
    const float dx = a[0] - b[0];
    const float dy = a[1] - b[1];
    const float dz = a[2] - b[2];
    return fmaf(dx, dx, fmaf(dy, dy, dz * dz));
}

// max d2 within one window row (3 points): reuses the bcast of point col0.
__device__ __forceinline__ float rowmax(const float p0[3], const float p1[3],
                                        const float p2[3], u64 neg1) {
    u64 a[3], b[3];
#pragma unroll
    for (int ch = 0; ch < 3; ch++) {
        a[ch] = bcast2(p0[ch]);
        b[ch] = pack2(p1[ch], p2[ch]);
    }
    float lo, hi;
    unpack2(lo, hi, d2p(a, b, neg1));
    return fmaxf(fmaxf(lo, hi), d2s(p1, p2));
}

__global__ __launch_bounds__(224, 5) void maxlocaldist_kernel(
    const float* __restrict__ x, float* __restrict__ out)
{
    const int w  = threadIdx.x;              // 0..223, one output column
    const int b  = blockIdx.z;
    const int h0 = blockIdx.y * R_ROWS;

    const float* xb = x + (long)b * 3 * HWD;
    const int cm = max(w - 1, 0);
    const int cp = min(w + 1, WD - 1);

    u64 neg1; { float m1 = -1.0f; neg1 = bcast2(m1); }

    // rolling 3-row window: pt[slot][col][ch], cols = {w-1, w, w+1}
    float pt[3][3][3];

    // preload input rows h0-1 (slot0) and h0 (slot1), clamped
#pragma unroll
    for (int s = 0; s < 2; s++) {
        const int r = max(h0 - 1 + s, 0);
#pragma unroll
        for (int ch = 0; ch < 3; ch++) {
            const float* row = xb + ch * HWD + r * WD;
            pt[s][0][ch] = __ldg(row + cm);
            pt[s][1][ch] = __ldg(row + w);
            pt[s][2][ch] = __ldg(row + cp);
        }
    }

    // cache: Wm = W(h-1), Wc = W(h), Xmc = X(h-1, h)
    float Wm = rowmax(pt[0][0], pt[0][1], pt[0][2], neg1);
    float Wc = rowmax(pt[1][0], pt[1][1], pt[1][2], neg1);
    float Xmc;
    {
        float m = d2s(pt[0][0], pt[1][0]);
#pragma unroll
        for (int ca = 0; ca < 3; ca++) {
            u64 a[3], q[3];
#pragma unroll
            for (int ch = 0; ch < 3; ch++) {
                a[ch] = bcast2(pt[1][ca][ch]);      // row h0 point ca
                q[ch] = pack2(pt[0][1][ch], pt[0][2][ch]);
            }
            float lo, hi;
            unpack2(lo, hi, d2p(a, q, neg1));
            m = fmaxf(m, fmaxf(lo, hi));
            if (ca < 2) m = fmaxf(m, d2s(pt[1][ca + 1], pt[0][0]));
        }
        Xmc = m;
    }

    const bool wborder = (w == 0) || (w == WD - 1);

#pragma unroll
    for (int rr = 0; rr < R_ROWS; rr++) {
        const int h     = h0 + rr;
        const int s_top = rr % 3;           // row h-1
        const int s_mid = (rr + 1) % 3;     // row h
        const int s_new = (rr + 2) % 3;     // row h+1 (loaded now)

        const int rn = min(h + 1, HD - 1);
#pragma unroll
        for (int ch = 0; ch < 3; ch++) {
            const float* row = xb + ch * HWD + rn * WD;
            pt[s_new][0][ch] = __ldg(row + cm);
            pt[s_new][1][ch] = __ldg(row + w);
            pt[s_new][2][ch] = __ldg(row + cp);
        }

        // packed cross terms: lo = d2(top, new), hi = d2(mid, new)
        float Xa, Xb;   // X(h-1,h+1), X(h,h+1)
        u64 Bn[3][3];   // bcast of new-row points per col per ch
#pragma unroll
        for (int cb = 0; cb < 3; cb++)
#pragma unroll
            for (int ch = 0; ch < 3; ch++)
                Bn[cb][ch] = bcast2(pt[s_new][cb][ch]);

        {
            float lo, hi;
            u64 A[3];
#pragma unroll
            for (int ch = 0; ch < 3; ch++)
                A[ch] = pack2(pt[s_top][0][ch], pt[s_mid][0][ch]);
            unpack2(Xa, Xb, d2p(Bn[0], A, neg1));
#pragma unroll
            for (int ca = 0; ca < 3; ca++) {
#pragma unroll
                for (int ch = 0; ch < 3; ch++)
                    A[ch] = pack2(pt[s_top][ca][ch], pt[s_mid][ca][ch]);
#pragma unroll
                for (int cb = 0; cb < 3; cb++) {
                    if (ca == 0 && cb == 0) continue;
                    unpack2(lo, hi, d2p(Bn[cb], A, neg1));
                    Xa = fmaxf(Xa, lo);
                    Xb = fmaxf(Xb, hi);
                }
            }
        }

        // W(h+1): reuse Bn[0]
        float Wn;
        {
            u64 q[3];
#pragma unroll
            for (int ch = 0; ch < 3; ch++)
                q[ch] = pack2(pt[s_new][1][ch], pt[s_new][2][ch]);
            float lo, hi;
            unpack2(lo, hi, d2p(Bn[0], q, neg1));
            Wn = fmaxf(fmaxf(lo, hi), d2s(pt[s_new][1], pt[s_new][2]));
        }

        const float m = fmaxf(fmaxf(fmaxf(Wm, Wc), fmaxf(Wn, Xmc)),
                              fmaxf(Xa, Xb));
        float v;
        asm("sqrt.approx.f32 %0, %1;" : "=f"(v) : "f"(m));

        const bool border = wborder || (h == 0) || (h == HD - 1);
        out[((long)b * HD + h) * WD + w] = border ? 0.0f : v;

        // rotate caches for next output row
        Wm = Wc; Wc = Wn; Xmc = Xb;
    }
}

extern "C" void kernel_launch(void* const* d_in, const int* in_sizes, int n_in,
                              void* d_out, int out_size)
{
    const float* x = (const float*)d_in[0];
    float* out = (float*)d_out;

    dim3 block(WD, 1, 1);                 // 224 threads = one full output row
    dim3 grid(1, NTILES, 32);             // 28 row-tiles x 32 batches = 896
    maxlocaldist_kernel<<<grid, block>>>(x, out);
}

// round 7
// speedup vs baseline: 1.0208x; 1.0208x over previous
#include <cuda_runtime.h>

// MaxLocaldist: per output pixel, max pairwise L2 distance among the 9 RGB
// pixels of the 3x3 neighborhood. Input (32,3,224,224) f32 NCHW.
// Output (32,1,224,224) f32, 1-pixel zero border.
//
// Row decomposition, thread-per-output-column, ZERO shfls:
//   W(r)      = max d2 among the 3 points of input row r      (3 pairs)
//   X(ra,rb)  = max d2 between rows ra and rb                 (9 pairs)
//   out(h)    = max(W(h-1),W(h),W(h+1), X(h-1,h), X(h-1,h+1), X(h,h+1))
// Sliding h->h+1 carries W(h), W(h+1), X(h,h+1) in 3 registers; only the 12
// pairs involving the new row h+1 are evaluated, packed into fma.rn.f32x2
// (bcast new-row point vs pack2(top-row point, mid-row point)).

#define HD 224
#define WD 224
#define HWD (HD * WD)
#define R_ROWS 8
#define NTILES (HD / R_ROWS)

typedef unsigned long long u64;

__device__ __forceinline__ u64 bcast2(float v) {
    u64 r; asm("mov.b64 %0, {%1, %1};" : "=l"(r) : "f"(v)); return r;
}
__device__ __forceinline__ u64 pack2(float lo, float hi) {
    u64 r; asm("mov.b64 %0, {%1, %2};" : "=l"(r) : "f"(lo), "f"(hi)); return r;
}
__device__ __forceinline__ void unpack2(float& lo, float& hi, u64 v) {
    asm("mov.b64 {%0, %1}, %2;" : "=f"(lo), "=f"(hi) : "l"(v));
}
__device__ __forceinline__ u64 fma2(u64 a, u64 b, u64 c) {
    u64 r; asm("fma.rn.f32x2 %0, %1, %2, %3;" : "=l"(r) : "l"(a), "l"(b), "l"(c));
    return r;
}
__device__ __forceinline__ u64 mul2(u64 a, u64 b) {
    u64 r; asm("mul.rn.f32x2 %0, %1, %2;" : "=l"(r) : "l"(a), "l"(b));
    return r;
}
// packed d2 between broadcast point a and packed point-pair b (exact sub via fma)
__device__ __forceinline__ u64 d2p(const u64 a[3], const u64 b[3], u64 neg1) {
    const u64 d0 = fma2(b[0], neg1, a[0]);
    const u64 d1 = fma2(b[1], neg1, a[1]);
    const u64 d2 = fma2(b[2], neg1, a[2]);
    u64 s = mul2(d2, d2);
    s = fma2(d1, d1, s);
    s = fma2(d0, d0, s);
    return s;
}
__device__ __forceinline__ float d2s(const float a[3], const float b[3]) {
    const float dx = a[0] - b[0];
    const float dy = a[1] - b[1];
    const float dz = a[2] - b[2];
    return fmaf(dx, dx, fmaf(dy, dy, dz * dz));
}

// max d2 within one window row (3 points): reuses the bcast of point col0.
__device__ __forceinline__ float rowmax(const float p0[3], const float p1[3],
                                        const float p2[3], u64 neg1) {
    u64 a[3], b[3];
#pragma unroll
    for (int ch = 0; ch < 3; ch++) {
        a[ch] = bcast2(p0[ch]);
        b[ch] = pack2(p1[ch], p2[ch]);
    }
    float lo, hi;
    unpack2(lo, hi, d2p(a, b, neg1));
    return fmaxf(fmaxf(lo, hi), d2s(p1, p2));
}

__global__ __launch_bounds__(224, 5) void maxlocaldist_kernel(
    const float* __restrict__ x, float* __restrict__ out)
{
    const int w  = threadIdx.x;              // 0..223, one output column
    const int b  = blockIdx.z;
    const int h0 = blockIdx.y * R_ROWS;

    const float* xb = x + (long)b * 3 * HWD;
    const int cm = max(w - 1, 0);
    const int cp = min(w + 1, WD - 1);

    u64 neg1; { float m1 = -1.0f; neg1 = bcast2(m1); }

    // rolling 3-row window: pt[slot][col][ch], cols = {w-1, w, w+1}
    float pt[3][3][3];

    // preload input rows h0-1 (slot0) and h0 (slot1), clamped
#pragma unroll
    for (int s = 0; s < 2; s++) {
        const int r = max(h0 - 1 + s, 0);
#pragma unroll
        for (int ch = 0; ch < 3; ch++) {
            const float* row = xb + ch * HWD + r * WD;
            pt[s][0][ch] = __ldg(row + cm);
            pt[s][1][ch] = __ldg(row + w);
            pt[s][2][ch] = __ldg(row + cp);
        }
    }

    // cache: Wm = W(h-1), Wc = W(h), Xmc = X(h-1, h)
    float Wm = rowmax(pt[0][0], pt[0][1], pt[0][2], neg1);
    float Wc = rowmax(pt[1][0], pt[1][1], pt[1][2], neg1);
    float Xmc;
    {
        float m = d2s(pt[0][0], pt[1][0]);
#pragma unroll
        for (int ca = 0; ca < 3; ca++) {
            u64 a[3], q[3];
#pragma unroll
            for (int ch = 0; ch < 3; ch++) {
                a[ch] = bcast2(pt[1][ca][ch]);      // row h0 point ca
                q[ch] = pack2(pt[0][1][ch], pt[0][2][ch]);
            }
            float lo, hi;
            unpack2(lo, hi, d2p(a, q, neg1));
            m = fmaxf(m, fmaxf(lo, hi));
            if (ca < 2) m = fmaxf(m, d2s(pt[1][ca + 1], pt[0][0]));
        }
        Xmc = m;
    }

    const bool wborder = (w == 0) || (w == WD - 1);

#pragma unroll
    for (int rr = 0; rr < R_ROWS; rr++) {
        const int h     = h0 + rr;
        const int s_top = rr % 3;           // row h-1
        const int s_mid = (rr + 1) % 3;     // row h
        const int s_new = (rr + 2) % 3;     // row h+1 (loaded now)

        const int rn = min(h + 1, HD - 1);
#pragma unroll
        for (int ch = 0; ch < 3; ch++) {
            const float* row = xb + ch * HWD + rn * WD;
            pt[s_new][0][ch] = __ldg(row + cm);
            pt[s_new][1][ch] = __ldg(row + w);
            pt[s_new][2][ch] = __ldg(row + cp);
        }

        // packed cross terms: lo = d2(top, new), hi = d2(mid, new)
        float Xa, Xb;   // X(h-1,h+1), X(h,h+1)
        u64 Bn[3][3];   // bcast of new-row points per col per ch
#pragma unroll
        for (int cb = 0; cb < 3; cb++)
#pragma unroll
            for (int ch = 0; ch < 3; ch++)
                Bn[cb][ch] = bcast2(pt[s_new][cb][ch]);

        {
            float lo, hi;
            u64 A[3];
#pragma unroll
            for (int ch = 0; ch < 3; ch++)
                A[ch] = pack2(pt[s_top][0][ch], pt[s_mid][0][ch]);
            unpack2(Xa, Xb, d2p(Bn[0], A, neg1));
#pragma unroll
            for (int ca = 0; ca < 3; ca++) {
#pragma unroll
                for (int ch = 0; ch < 3; ch++)
                    A[ch] = pack2(pt[s_top][ca][ch], pt[s_mid][ca][ch]);
#pragma unroll
                for (int cb = 0; cb < 3; cb++) {
                    if (ca == 0 && cb == 0) continue;
                    unpack2(lo, hi, d2p(Bn[cb], A, neg1));
                    Xa = fmaxf(Xa, lo);
                    Xb = fmaxf(Xb, hi);
                }
            }
        }

        // W(h+1): reuse Bn[0]
        float Wn;
        {
            u64 q[3];
#pragma unroll
            for (int ch = 0; ch < 3; ch++)
                q[ch] = pack2(pt[s_new][1][ch], pt[s_new][2][ch]);
            float lo, hi;
            unpack2(lo, hi, d2p(Bn[0], q, neg1));
            Wn = fmaxf(fmaxf(lo, hi), d2s(pt[s_new][1], pt[s_new][2]));
        }

        const float m = fmaxf(fmaxf(fmaxf(Wm, Wc), fmaxf(Wn, Xmc)),
                              fmaxf(Xa, Xb));
        float v;
        asm("sqrt.approx.f32 %0, %1;" : "=f"(v) : "f"(m));

        const bool border = wborder || (h == 0) || (h == HD - 1);
        out[((long)b * HD + h) * WD + w] = border ? 0.0f : v;

        // rotate caches for next output row
        Wm = Wc; Wc = Wn; Xmc = Xb;
    }
}

extern "C" void kernel_launch(void* const* d_in, const int* in_sizes, int n_in,
                              void* d_out, int out_size)
{
    const float* x = (const float*)d_in[0];
    float* out = (float*)d_out;

    dim3 block(WD, 1, 1);                 // 224 threads = one full output row
    dim3 grid(1, NTILES, 32);             // 28 row-tiles x 32 batches = 896
    maxlocaldist_kernel<<<grid, block>>>(x, out);
}

// round 8
// speedup vs baseline: 1.0243x; 1.0035x over previous
#include <cuda_runtime.h>

// MaxLocaldist: per output pixel, max pairwise L2 distance among the 9 RGB
// pixels of the 3x3 neighborhood. Input (32,3,224,224) f32 NCHW.
// Output (32,1,224,224) f32, 1-pixel zero border.
//
// Column-pair decomposition with temporal d2 caching (12 pair-evals/output,
// shared across lanes via 3 shfls), but the POINT WINDOW lives in a 4-slot
// rolling SHARED buffer staged cooperatively (3 LDG + 3 STS per thread per
// row, 1 barrier). Per-thread register state is only the d2 caches
// (D01[9]+D02[9]+sd[3]) -> regs ~48 -> 5 blocks/SM, ~62% occupancy
// (vs 40% for the register-window variants, which were latency-bound).

#define HD 224
#define WD 224
#define HWD (HD * WD)
#define R_ROWS 10
#define NTILES 23          // ceil(224/10)
#define FULLMASK 0xffffffffu

__device__ __forceinline__ float d2s(const float a[3], const float b[3]) {
    const float dx = a[0] - b[0];
    const float dy = a[1] - b[1];
    const float dz = a[2] - b[2];
    return fmaf(dx, dx, fmaf(dy, dy, dz * dz));
}

__global__ __launch_bounds__(256, 5) void maxlocaldist_kernel(
    const float* __restrict__ x, float* __restrict__ out)
{
    __shared__ float sm[4][3][WD];      // [slot][channel][col]

    const int tid  = threadIdx.x;
    const int lane = tid & 31;
    const int wgrp = tid >> 5;          // 0..7, 30 output cols per warp
    const int b    = blockIdx.z;
    const int h0   = blockIdx.y * R_ROWS;
    const int c0   = wgrp * 30 + lane;  // this lane's base column (may exceed 223)
    const int cc0  = min(c0,     WD - 1);
    const int cc1  = min(c0 + 1, WD - 1);
    const int cc2  = min(c0 + 2, WD - 1);

    const float* xb = x + (long)b * 3 * HWD;
    const bool loader = (tid < WD);

    // ---- prologue: input rows t=0 (h0-1, clamped) and t=1 (h0) -> slots 0,1
#pragma unroll
    for (int t = 0; t < 2; t++) {
        const int r = min(max(h0 - 1 + t, 0), HD - 1);
        if (loader) {
#pragma unroll
            for (int ch = 0; ch < 3; ch++)
                sm[t][ch][tid] = __ldg(xb + ch * HWD + r * WD + tid);
        }
    }
    __syncthreads();

    // d2 caches: D01[row-slot of col0][row-slot of col1], D02 likewise,
    // sd[s] = within-col0 d2 of the pair NOT involving slot s.
    float D01[3][3], D02[3][3], sd[3];
    {
        float p0[2][3], p1[2][3], p2[2][3];
#pragma unroll
        for (int t = 0; t < 2; t++)
#pragma unroll
            for (int ch = 0; ch < 3; ch++) {
                p0[t][ch] = sm[t][ch][cc0];
                p1[t][ch] = sm[t][ch][cc1];
                p2[t][ch] = sm[t][ch][cc2];
            }
#pragma unroll
        for (int s = 0; s < 2; s++)
#pragma unroll
            for (int c = 0; c < 2; c++) {
                D01[s][c] = d2s(p0[s], p1[c]);
                D02[s][c] = d2s(p0[s], p2[c]);
            }
        sd[2] = d2s(p0[0], p0[1]);      // pair (t=0, t=1), excluded slot 2
    }

    const int  w_out   = c0 + 1;
    const bool wvalid  = (lane < 30) && (w_out <= WD - 1);
    const bool zerocol = (wgrp == 0) && (lane == 31);

#pragma unroll
    for (int rr = 0; rr < R_ROWS; rr++) {
        const int h   = h0 + rr;
        const int smN = (rr + 2) & 3;   // smem slot of new row t=rr+2
        const int smA = rr & 3;         // row t=rr   (top)
        const int smB = (rr + 1) & 3;   // row t=rr+1 (mid)
        const int X   = (rr + 2) % 3;   // cache slot of new row
        const int A   = rr % 3;
        const int B   = (rr + 1) % 3;

        // stage input row h+1 (clamped) into slot smN
        const int rn = min(h + 1, HD - 1);
        if (loader) {
#pragma unroll
            for (int ch = 0; ch < 3; ch++)
                sm[smN][ch][tid] = __ldg(xb + ch * HWD + rn * WD + tid);
        }
        __syncthreads();

        // read the points needed by the 12 refresh evals
        float nx0[3], nx1[3], nx2[3], pA0[3], pB0[3];
#pragma unroll
        for (int ch = 0; ch < 3; ch++) {
            nx0[ch] = sm[smN][ch][cc0];
            nx1[ch] = sm[smN][ch][cc1];
            nx2[ch] = sm[smN][ch][cc2];
            pA0[ch] = sm[smA][ch][cc0];
            pB0[ch] = sm[smB][ch][cc0];
        }
        {
            float pA1[3], pB1[3];
#pragma unroll
            for (int ch = 0; ch < 3; ch++) {
                pA1[ch] = sm[smA][ch][cc1];
                pB1[ch] = sm[smB][ch][cc1];
            }
            D01[X][A] = d2s(nx0, pA1);
            D01[X][B] = d2s(nx0, pB1);
            D01[X][X] = d2s(nx0, nx1);
            D01[A][X] = d2s(pA0, nx1);
            D01[B][X] = d2s(pB0, nx1);
        }
        {
            float pA2[3], pB2[3];
#pragma unroll
            for (int ch = 0; ch < 3; ch++) {
                pA2[ch] = sm[smA][ch][cc2];
                pB2[ch] = sm[smB][ch][cc2];
            }
            D02[X][A] = d2s(nx0, pA2);
            D02[X][B] = d2s(nx0, pB2);
            D02[X][X] = d2s(nx0, nx2);
            D02[A][X] = d2s(pA0, nx2);
            D02[B][X] = d2s(pB0, nx2);
        }
        sd[B] = d2s(nx0, pA0);          // pair (t=rr,   t=rr+2)
        sd[A] = d2s(nx0, pB0);          // pair (t=rr+1, t=rr+2)
        // sd[X] = pair (t=rr, t=rr+1), carried from the previous iteration

        const float S = fmaxf(fmaxf(sd[0], sd[1]), sd[2]);
        float P01 = D01[0][0], P02 = D02[0][0];
#pragma unroll
        for (int s = 0; s < 3; s++)
#pragma unroll
            for (int c = 0; c < 3; c++)
                if (s | c) {
                    P01 = fmaxf(P01, D01[s][c]);
                    P02 = fmaxf(P02, D02[s][c]);
                }

        const float S1 = __shfl_down_sync(FULLMASK, S,   1);
        const float S2 = __shfl_down_sync(FULLMASK, S,   2);
        const float Q  = __shfl_down_sync(FULLMASK, P01, 1);

        const float m = fmaxf(fmaxf(fmaxf(S, S1), fmaxf(S2, P01)),
                              fmaxf(Q, P02));
        float v;
        asm("sqrt.approx.f32 %0, %1;" : "=f"(v) : "f"(m));

        if (h < HD) {
            const bool border = (h == 0) || (h == HD - 1) || (w_out == WD - 1);
            if (wvalid)
                out[((long)b * HD + h) * WD + w_out] = border ? 0.0f : v;
            if (zerocol)
                out[((long)b * HD + h) * WD] = 0.0f;
        }
    }
}

extern "C" void kernel_launch(void* const* d_in, const int* in_sizes, int n_in,
                              void* d_out, int out_size)
{
    const float* x = (const float*)d_in[0];
    float* out = (float*)d_out;

    dim3 block(256, 1, 1);
    dim3 grid(1, NTILES, 32);   // 23 x 32 = 736 blocks ~= one wave at 5 blocks/SM
    maxlocaldist_kernel<<<grid, block>>>(x, out);
}

// round 9
// speedup vs baseline: 1.2888x; 1.2582x over previous
#include <cuda_runtime.h>

// MaxLocaldist: per output pixel, max pairwise L2 distance among the 9 RGB
// pixels of the 3x3 neighborhood. Input (32,3,224,224) f32 NCHW.
// Output (32,1,224,224) f32, 1-pixel zero border.
//
// Column-pair decomposition + temporal d2 caching (12 pair-evals/output,
// shared across lanes via 3 shfls) — as R3 — with SOFTWARE PIPELINING:
// the 9 loads for input row h+2 are issued at the TOP of each iteration,
// into the pt slot that is dead at that point (it held row h-1, whose cache
// entries already exist). The output-h compute (max trees + shfl + sqrt +
// store, ~60 instrs) runs between load issue and load consumption, hiding
// the L1/L2 latency that previously stalled the refresh every row.

#define HD 224
#define WD 224
#define HWD (HD * WD)
#define R_ROWS 8
#define FULLMASK 0xffffffffu

__device__ __forceinline__ float d2s(const float a[3], const float b[3]) {
    const float dx = a[0] - b[0];
    const float dy = a[1] - b[1];
    const float dz = a[2] - b[2];
    return fmaf(dx, dx, fmaf(dy, dy, dz * dz));
}

__global__ __launch_bounds__(256, 4) void maxlocaldist_kernel(
    const float* __restrict__ x, float* __restrict__ out)
{
    const int lane = threadIdx.x & 31;
    const int wgrp = threadIdx.x >> 5;          // 0..7: column group
    const int b    = blockIdx.z;
    const int h0   = blockIdx.y * R_ROWS;
    const int c0   = wgrp * 30 + lane;

    const float* xb = x + (long)b * 3 * HWD;

    int col[3];
#pragma unroll
    for (int j = 0; j < 3; j++) col[j] = min(c0 + j, WD - 1);

    // rolling 3-row window: pt[slot][col][ch]
    float pt[3][3][3];

    // preload input rows h0-1, h0, h0+1 (clamped) into slots 0,1,2
#pragma unroll
    for (int s = 0; s < 3; s++) {
        const int r = min(max(h0 - 1 + s, 0), HD - 1);
#pragma unroll
        for (int ch = 0; ch < 3; ch++)
#pragma unroll
            for (int j = 0; j < 3; j++)
                pt[s][j][ch] = __ldg(xb + ch * HWD + r * WD + col[j]);
    }

    // d2 caches over the current 3-slot window
    float D01[3][3];   // [slot of col0][slot of col1]
    float D02[3][3];   // [slot of col0][slot of col2]
    float sd[3];       // within-col0 pair d2, indexed by the EXCLUDED slot
#pragma unroll
    for (int a = 0; a < 3; a++)
#pragma unroll
        for (int c = 0; c < 3; c++) {
            D01[a][c] = d2s(pt[a][0], pt[c][1]);
            D02[a][c] = d2s(pt[a][0], pt[c][2]);
        }
    sd[2] = d2s(pt[0][0], pt[1][0]);
    sd[1] = d2s(pt[0][0], pt[2][0]);
    sd[0] = d2s(pt[1][0], pt[2][0]);

    const int  w_out   = c0 + 1;
    const bool wvalid  = (lane < 30) && (w_out <= WD - 1);
    const bool zerocol = (wgrp == 0) && (lane == 31);

#pragma unroll
    for (int rr = 0; rr < R_ROWS; rr++) {
        const int h  = h0 + rr;
        const int X  = rr % 3;          // dead slot (held row h-1) -> row h+2
        const int a1 = (rr + 1) % 3;    // row h
        const int a2 = (rr + 2) % 3;    // row h+1

        // ---- PIPELINE STAGE 1: issue loads for row h+2 into the dead slot.
        // Not consumed until after the output-h compute below.
        if (rr < R_ROWS - 1) {
            const int rn = min(h + 2, HD - 1);
#pragma unroll
            for (int ch = 0; ch < 3; ch++)
#pragma unroll
                for (int j = 0; j < 3; j++)
                    pt[X][j][ch] = __ldg(xb + ch * HWD + rn * WD + col[j]);
        }

        // ---- PIPELINE STAGE 2: compute output h from the caches only.
        const float S = fmaxf(fmaxf(sd[0], sd[1]), sd[2]);

        float P01 = D01[0][0], P02 = D02[0][0];
#pragma unroll
        for (int a = 0; a < 3; a++)
#pragma unroll
            for (int c = 0; c < 3; c++)
                if (a | c) {
                    P01 = fmaxf(P01, D01[a][c]);
                    P02 = fmaxf(P02, D02[a][c]);
                }

        const float S1 = __shfl_down_sync(FULLMASK, S,   1);
        const float S2 = __shfl_down_sync(FULLMASK, S,   2);
        const float Q  = __shfl_down_sync(FULLMASK, P01, 1);

        const float m = fmaxf(fmaxf(fmaxf(S, S1), fmaxf(S2, P01)),
                              fmaxf(Q, P02));
        float v;
        asm("sqrt.approx.f32 %0, %1;" : "=f"(v) : "f"(m));

        const bool border = (h == 0) || (h == HD - 1) || (w_out == WD - 1);
        if (wvalid)
            out[((long)b * HD + h) * WD + w_out] = border ? 0.0f : v;
        if (zerocol)
            out[((long)b * HD + h) * WD] = 0.0f;

        // ---- PIPELINE STAGE 3: refresh caches with the (now landed) loads.
        if (rr < R_ROWS - 1) {
#pragma unroll
            for (int c = 0; c < 3; c++) {
                D01[X][c] = d2s(pt[X][0], pt[c][1]);   // new col0 row vs all col1
                D02[X][c] = d2s(pt[X][0], pt[c][2]);
            }
            D01[a1][X] = d2s(pt[a1][0], pt[X][1]);     // old col0 rows vs new col1
            D01[a2][X] = d2s(pt[a2][0], pt[X][1]);
            D02[a1][X] = d2s(pt[a1][0], pt[X][2]);
            D02[a2][X] = d2s(pt[a2][0], pt[X][2]);

            sd[a2] = d2s(pt[X][0], pt[a1][0]);         // new within-col pairs
            sd[a1] = d2s(pt[X][0], pt[a2][0]);
            // sd[X] (pair a1,a2) survives unchanged
        }
    }
}

extern "C" void kernel_launch(void* const* d_in, const int* in_sizes, int n_in,
                              void* d_out, int out_size)
{
    const float* x = (const float*)d_in[0];
    float* out = (float*)d_out;

    dim3 block(256, 1, 1);
    dim3 grid(1, HD / R_ROWS, 32);
    maxlocaldist_kernel<<<grid, block>>>(x, out);
}

// round 10
// speedup vs baseline: 1.3002x; 1.0088x over previous
#include <cuda_runtime.h>

// MaxLocaldist: per output pixel, max pairwise L2 distance among the 9 RGB
// pixels of the 3x3 neighborhood. Input (32,3,224,224) f32 NCHW.
// Output (32,1,224,224) f32, 1-pixel zero border.
//
// Column-pair decomposition + temporal d2 caching (12 pair-evals/output,
// shared across lanes via 3 shfls) — as R3 — with SOFTWARE PIPELINING:
// the 9 loads for input row h+2 are issued at the TOP of each iteration,
// into the pt slot that is dead at that point (it held row h-1, whose cache
// entries already exist). The output-h compute (max trees + shfl + sqrt +
// store, ~60 instrs) runs between load issue and load consumption, hiding
// the L1/L2 latency that previously stalled the refresh every row.

#define HD 224
#define WD 224
#define HWD (HD * WD)
#define R_ROWS 8
#define FULLMASK 0xffffffffu

__device__ __forceinline__ float d2s(const float a[3], const float b[3]) {
    const float dx = a[0] - b[0];
    const float dy = a[1] - b[1];
    const float dz = a[2] - b[2];
    return fmaf(dx, dx, fmaf(dy, dy, dz * dz));
}

__global__ __launch_bounds__(256, 4) void maxlocaldist_kernel(
    const float* __restrict__ x, float* __restrict__ out)
{
    const int lane = threadIdx.x & 31;
    const int wgrp = threadIdx.x >> 5;          // 0..7: column group
    const int b    = blockIdx.z;
    const int h0   = blockIdx.y * R_ROWS;
    const int c0   = wgrp * 30 + lane;

    const float* xb = x + (long)b * 3 * HWD;

    int col[3];
#pragma unroll
    for (int j = 0; j < 3; j++) col[j] = min(c0 + j, WD - 1);

    // rolling 3-row window: pt[slot][col][ch]
    float pt[3][3][3];

    // preload input rows h0-1, h0, h0+1 (clamped) into slots 0,1,2
#pragma unroll
    for (int s = 0; s < 3; s++) {
        const int r = min(max(h0 - 1 + s, 0), HD - 1);
#pragma unroll
        for (int ch = 0; ch < 3; ch++)
#pragma unroll
            for (int j = 0; j < 3; j++)
                pt[s][j][ch] = __ldg(xb + ch * HWD + r * WD + col[j]);
    }

    // d2 caches over the current 3-slot window
    float D01[3][3];   // [slot of col0][slot of col1]
    float D02[3][3];   // [slot of col0][slot of col2]
    float sd[3];       // within-col0 pair d2, indexed by the EXCLUDED slot
#pragma unroll
    for (int a = 0; a < 3; a++)
#pragma unroll
        for (int c = 0; c < 3; c++) {
            D01[a][c] = d2s(pt[a][0], pt[c][1]);
            D02[a][c] = d2s(pt[a][0], pt[c][2]);
        }
    sd[2] = d2s(pt[0][0], pt[1][0]);
    sd[1] = d2s(pt[0][0], pt[2][0]);
    sd[0] = d2s(pt[1][0], pt[2][0]);

    const int  w_out   = c0 + 1;
    const bool wvalid  = (lane < 30) && (w_out <= WD - 1);
    const bool zerocol = (wgrp == 0) && (lane == 31);

#pragma unroll
    for (int rr = 0; rr < R_ROWS; rr++) {
        const int h  = h0 + rr;
        const int X  = rr % 3;          // dead slot (held row h-1) -> row h+2
        const int a1 = (rr + 1) % 3;    // row h
        const int a2 = (rr + 2) % 3;    // row h+1

        // ---- PIPELINE STAGE 1: issue loads for row h+2 into the dead slot.
        // Not consumed until after the output-h compute below.
        if (rr < R_ROWS - 1) {
            const int rn = min(h + 2, HD - 1);
#pragma unroll
            for (int ch = 0; ch < 3; ch++)
#pragma unroll
                for (int j = 0; j < 3; j++)
                    pt[X][j][ch] = __ldg(xb + ch * HWD + rn * WD + col[j]);
        }

        // ---- PIPELINE STAGE 2: compute output h from the caches only.
        const float S = fmaxf(fmaxf(sd[0], sd[1]), sd[2]);

        float P01 = D01[0][0], P02 = D02[0][0];
#pragma unroll
        for (int a = 0; a < 3; a++)
#pragma unroll
            for (int c = 0; c < 3; c++)
                if (a | c) {
                    P01 = fmaxf(P01, D01[a][c]);
                    P02 = fmaxf(P02, D02[a][c]);
                }

        const float S1 = __shfl_down_sync(FULLMASK, S,   1);
        const float S2 = __shfl_down_sync(FULLMASK, S,   2);
        const float Q  = __shfl_down_sync(FULLMASK, P01, 1);

        const float m = fmaxf(fmaxf(fmaxf(S, S1), fmaxf(S2, P01)),
                              fmaxf(Q, P02));
        float v;
        asm("sqrt.approx.f32 %0, %1;" : "=f"(v) : "f"(m));

        const bool border = (h == 0) || (h == HD - 1) || (w_out == WD - 1);
        if (wvalid)
            out[((long)b * HD + h) * WD + w_out] = border ? 0.0f : v;
        if (zerocol)
            out[((long)b * HD + h) * WD] = 0.0f;

        // ---- PIPELINE STAGE 3: refresh caches with the (now landed) loads.
        if (rr < R_ROWS - 1) {
#pragma unroll
            for (int c = 0; c < 3; c++) {
                D01[X][c] = d2s(pt[X][0], pt[c][1]);   // new col0 row vs all col1
                D02[X][c] = d2s(pt[X][0], pt[c][2]);
            }
            D01[a1][X] = d2s(pt[a1][0], pt[X][1]);     // old col0 rows vs new col1
            D01[a2][X] = d2s(pt[a2][0], pt[X][1]);
            D02[a1][X] = d2s(pt[a1][0], pt[X][2]);
            D02[a2][X] = d2s(pt[a2][0], pt[X][2]);

            sd[a2] = d2s(pt[X][0], pt[a1][0]);         // new within-col pairs
            sd[a1] = d2s(pt[X][0], pt[a2][0]);
            // sd[X] (pair a1,a2) survives unchanged
        }
    }
}

extern "C" void kernel_launch(void* const* d_in, const int* in_sizes, int n_in,
                              void* d_out, int out_size)
{
    const float* x = (const float*)d_in[0];
    float* out = (float*)d_out;

    dim3 block(256, 1, 1);
    dim3 grid(1, HD / R_ROWS, 32);
    maxlocaldist_kernel<<<grid, block>>>(x, out);
}